// round 11
// baseline (speedup 1.0000x reference)
#include <cuda_runtime.h>
#include <math.h>

// Problem constants
#define CB   2
#define CS   2048
#define CD   1024
#define CH   16
#define CDK  64
#define BIAS_LEN (2*CS - 1)   // 4095 relative distances

// ---------------- scratch (static device globals; no runtime allocation) ----
__device__ __align__(16) float g_Q[(size_t)CB*CH*CS*CDK];
__device__ __align__(16) float g_K[(size_t)CB*CH*CS*CDK];
__device__ __align__(16) float g_V[(size_t)CB*CH*CS*CDK];
__device__ __align__(16) float g_AO[(size_t)CB*CS*CD];
__device__ __align__(16) float g_bias[CH*BIAS_LEN];

// ---------------- T5 relative position bias table --------------------------
// g_bias[h][t] = rel_bias[bucket(d)][h],  d = t - (CS-1), bidirectional buckets
__global__ void bias_table_kernel(const float* __restrict__ rel_bias)
{
    int idx = blockIdx.x * blockDim.x + threadIdx.x;
    if (idx >= CH * BIAS_LEN) return;
    int h = idx / BIAS_LEN;
    int t = idx - h * BIAS_LEN;
    int d = t - (CS - 1);

    int base = (d > 0) ? 16 : 0;       // num_buckets/2 for positive rel pos
    int a = (d < 0) ? -d : d;
    int bucket;
    if (a < 8) {                        // max_exact = 8
        bucket = a;
    } else {
        // replicate jax fp32 math: log(a/8) / log(16) * 8, truncated to int
        float v = logf((float)a * 0.125f);
        v = v / 2.772588722239781f;     // ln(16)
        v = v * 8.0f;
        int bl = 8 + (int)v;
        bucket = (bl > 15) ? 15 : bl;
    }
    g_bias[h * BIAS_LEN + t] = rel_bias[(base + bucket) * CH + h];
}

// ---------------- SGEMM: 128x128 block tile, BK=8, 8x8 micro-tile ----------
#define GBM 128
#define GBN 128
#define GBK 8

__device__ __forceinline__ void sgemm_body(
    const float* __restrict__ A, const float* __restrict__ W,
    float* __restrict__ C, int N, int K, int scatter)
{
    __shared__ float As[GBK][GBM];
    __shared__ float Bs[GBK][GBN];
    const int tid = threadIdx.x;       // 256 threads
    const int tx = tid & 15;
    const int ty = tid >> 4;
    const float* Ab = A + (size_t)blockIdx.y * GBM * K;
    const float* Wb = W + blockIdx.x * GBN;

    float acc[8][8];
    #pragma unroll
    for (int i = 0; i < 8; i++)
        #pragma unroll
        for (int j = 0; j < 8; j++) acc[i][j] = 0.f;

    const int aRow = tid >> 1;          // 0..127
    const int aCol = (tid & 1) << 2;    // 0 or 4
    const int bRow = tid >> 5;          // 0..7
    const int bCol = (tid & 31) << 2;   // 0..124

    for (int k0 = 0; k0 < K; k0 += GBK) {
        float4 a4 = *(const float4*)(Ab + (size_t)aRow * K + k0 + aCol);
        As[aCol + 0][aRow] = a4.x;
        As[aCol + 1][aRow] = a4.y;
        As[aCol + 2][aRow] = a4.z;
        As[aCol + 3][aRow] = a4.w;
        *(float4*)(&Bs[bRow][bCol]) =
            *(const float4*)(Wb + (size_t)(k0 + bRow) * N + bCol);
        __syncthreads();
        #pragma unroll
        for (int kk = 0; kk < GBK; kk++) {
            float ar[8], br[8];
            *(float4*)&ar[0] = *(const float4*)&As[kk][ty * 8];
            *(float4*)&ar[4] = *(const float4*)&As[kk][ty * 8 + 4];
            *(float4*)&br[0] = *(const float4*)&Bs[kk][tx * 8];
            *(float4*)&br[4] = *(const float4*)&Bs[kk][tx * 8 + 4];
            #pragma unroll
            for (int i = 0; i < 8; i++)
                #pragma unroll
                for (int j = 0; j < 8; j++)
                    acc[i][j] = fmaf(ar[i], br[j], acc[i][j]);
        }
        __syncthreads();
    }

    if (!scatter) {
        #pragma unroll
        for (int i = 0; i < 8; i++) {
            int m = blockIdx.y * GBM + ty * 8 + i;
            float* Crow = C + (size_t)m * N + blockIdx.x * GBN + tx * 8;
            *(float4*)(Crow)     = make_float4(acc[i][0], acc[i][1], acc[i][2], acc[i][3]);
            *(float4*)(Crow + 4) = make_float4(acc[i][4], acc[i][5], acc[i][6], acc[i][7]);
        }
    } else {
        // scatter [m = b*S+s, n = h*64+dk]  ->  [B,H,S,DK]
        #pragma unroll
        for (int i = 0; i < 8; i++) {
            int m = blockIdx.y * GBM + ty * 8 + i;
            int b = m >> 11;
            int s = m & (CS - 1);
            int n = blockIdx.x * GBN + tx * 8;   // 8 cols stay inside one head (64 % 8 == 0)
            int h = n >> 6;
            int dk = n & 63;
            float* Crow = C + ((((size_t)b * CH + h) * CS + s) * CDK + dk);
            *(float4*)(Crow)     = make_float4(acc[i][0], acc[i][1], acc[i][2], acc[i][3]);
            *(float4*)(Crow + 4) = make_float4(acc[i][4], acc[i][5], acc[i][6], acc[i][7]);
        }
    }
}

__global__ void __launch_bounds__(256) qkv_kernel(
    const float* __restrict__ X,
    const float* __restrict__ Wq, const float* __restrict__ Wk,
    const float* __restrict__ Wv)
{
    const float* W = (blockIdx.z == 0) ? Wq : (blockIdx.z == 1) ? Wk : Wv;
    float* O = (blockIdx.z == 0) ? g_Q : (blockIdx.z == 1) ? g_K : g_V;
    sgemm_body(X, W, O, CD, CD, 1);
}

__global__ void __launch_bounds__(256) out_proj_kernel(
    const float* __restrict__ Wo, float* __restrict__ out)
{
    sgemm_body(g_AO, Wo, out, CD, CD, 0);
}

// ---------------- fused flash attention (fp32, online softmax) -------------
#define AQ  64          // q rows per block
#define AK  64          // k rows per tile
#define ALD 68          // padded smem row (bank-conflict-free broadcasts)

struct AttnSmem {
    float Qs[CDK][ALD];   // Q transposed: Qs[d][r]
    float Ks[CDK][ALD];   // K transposed: Ks[d][c]
    float Vs[AK][ALD];    // Vs[kk][d]
    float Ps[AQ][ALD];    // probabilities: Ps[r][kk]
    float bias[CS + AQ];  // 2112 bias slice entries for this q-tile
};

__global__ void __launch_bounds__(256) attn_kernel()
{
    extern __shared__ char smem_raw[];
    AttnSmem* sm = reinterpret_cast<AttnSmem*>(smem_raw);

    const int tid = threadIdx.x;       // 256 threads: 16x16, 4x4 micro-tiles
    const int tx = tid & 15;
    const int ty = tid >> 4;
    const int i0 = blockIdx.x * AQ;
    const int h  = blockIdx.y;
    const int b  = blockIdx.z;

    const size_t head_off = ((size_t)b * CH + h) * CS * CDK;
    const float* Qg = g_Q + head_off + (size_t)i0 * CDK;
    const float* Kg = g_K + head_off;
    const float* Vg = g_V + head_off;

    // load Q tile transposed: Qs[d][r]
    for (int v = tid; v < AQ * (CDK / 4); v += 256) {
        int r  = v >> 4;
        int d4 = (v & 15) << 2;
        float4 q4 = *(const float4*)(Qg + r * CDK + d4);
        sm->Qs[d4 + 0][r] = q4.x;
        sm->Qs[d4 + 1][r] = q4.y;
        sm->Qs[d4 + 2][r] = q4.z;
        sm->Qs[d4 + 3][r] = q4.w;
    }
    // load bias slice: bias[t] covers d = (j - q) for this q-tile,
    // t = j + (AQ-1) - r_local;  table index = t + CS - i0 - AQ  (in [0,4094])
    for (int t = tid; t < CS - 1 + AQ; t += 256)
        sm->bias[t] = g_bias[h * BIAS_LEN + t + CS - i0 - AQ];

    float m[4], l[4], o[4][4];
    #pragma unroll
    for (int i = 0; i < 4; i++) {
        m[i] = -1e30f;
        l[i] = 0.f;
        #pragma unroll
        for (int j = 0; j < 4; j++) o[i][j] = 0.f;
    }

    for (int kt = 0; kt < CS / AK; kt++) {
        const int kj0 = kt * AK;
        __syncthreads();   // prev-iter AV done with Ps/Vs; Q/bias loads not yet needed

        // load K (transposed) + V tiles
        for (int v = tid; v < AK * (CDK / 4); v += 256) {
            int row = v >> 4;
            int d4  = (v & 15) << 2;
            float4 k4 = *(const float4*)(Kg + (size_t)(kj0 + row) * CDK + d4);
            sm->Ks[d4 + 0][row] = k4.x;
            sm->Ks[d4 + 1][row] = k4.y;
            sm->Ks[d4 + 2][row] = k4.z;
            sm->Ks[d4 + 3][row] = k4.w;
            *(float4*)&sm->Vs[row][d4] =
                *(const float4*)(Vg + (size_t)(kj0 + row) * CDK + d4);
        }
        __syncthreads();

        // S = Q @ K^T  (4x4 per thread)
        float s[4][4];
        #pragma unroll
        for (int i = 0; i < 4; i++)
            #pragma unroll
            for (int j = 0; j < 4; j++) s[i][j] = 0.f;

        #pragma unroll 8
        for (int d = 0; d < CDK; d++) {
            const float4 aq = *(const float4*)&sm->Qs[d][ty * 4];
            const float4 bk = *(const float4*)&sm->Ks[d][tx * 4];
            float ar[4] = {aq.x, aq.y, aq.z, aq.w};
            float br[4] = {bk.x, bk.y, bk.z, bk.w};
            #pragma unroll
            for (int i = 0; i < 4; i++)
                #pragma unroll
                for (int j = 0; j < 4; j++)
                    s[i][j] = fmaf(ar[i], br[j], s[i][j]);
        }

        // + position bias (T5: no 1/sqrt(dk) scaling)
        #pragma unroll
        for (int i = 0; i < 4; i++) {
            int tb = kj0 + tx * 4 + (AQ - 1) - (ty * 4 + i);
            #pragma unroll
            for (int j = 0; j < 4; j++)
                s[i][j] += sm->bias[tb + j];
        }

        // online softmax: rows r = ty*4+i are owned by 16 consecutive lanes
        // (same ty). xor-shuffles {8,4,2,1} reduce within that 16-lane group.
        #pragma unroll
        for (int i = 0; i < 4; i++) {
            float mloc = fmaxf(fmaxf(s[i][0], s[i][1]), fmaxf(s[i][2], s[i][3]));
            #pragma unroll
            for (int off = 8; off >= 1; off >>= 1)
                mloc = fmaxf(mloc, __shfl_xor_sync(0xffffffffu, mloc, off));
            float mnew = fmaxf(m[i], mloc);
            float sc = __expf(m[i] - mnew);
            m[i] = mnew;
            float ps = 0.f;
            #pragma unroll
            for (int j = 0; j < 4; j++) {
                float p = __expf(s[i][j] - mnew);
                s[i][j] = p;
                ps += p;
            }
            #pragma unroll
            for (int off = 8; off >= 1; off >>= 1)
                ps += __shfl_xor_sync(0xffffffffu, ps, off);
            l[i] = l[i] * sc + ps;
            #pragma unroll
            for (int j = 0; j < 4; j++) o[i][j] *= sc;
        }

        // stash probabilities
        #pragma unroll
        for (int i = 0; i < 4; i++)
            *(float4*)&sm->Ps[ty * 4 + i][tx * 4] =
                make_float4(s[i][0], s[i][1], s[i][2], s[i][3]);
        __syncthreads();

        // O += P @ V
        #pragma unroll 8
        for (int kk = 0; kk < AK; kk++) {
            const float4 bv = *(const float4*)&sm->Vs[kk][tx * 4];
            float br[4] = {bv.x, bv.y, bv.z, bv.w};
            float ar[4];
            #pragma unroll
            for (int i = 0; i < 4; i++) ar[i] = sm->Ps[ty * 4 + i][kk];
            #pragma unroll
            for (int i = 0; i < 4; i++)
                #pragma unroll
                for (int j = 0; j < 4; j++)
                    o[i][j] = fmaf(ar[i], br[j], o[i][j]);
        }
    }

    // epilogue: normalize, write [b, s, h*64+dk] (ready for Wo GEMM)
    #pragma unroll
    for (int i = 0; i < 4; i++) {
        float inv = 1.f / l[i];
        int srow = i0 + ty * 4 + i;
        float* dst = g_AO + ((size_t)b * CS + srow) * CD + h * CDK + tx * 4;
        *(float4*)dst = make_float4(o[i][0] * inv, o[i][1] * inv,
                                    o[i][2] * inv, o[i][3] * inv);
    }
}

// ---------------- launch ----------------------------------------------------
extern "C" void kernel_launch(void* const* d_in, const int* in_sizes, int n_in,
                              void* d_out, int out_size)
{
    (void)in_sizes; (void)n_in; (void)out_size;
    const float* X  = (const float*)d_in[0];
    const float* Wq = (const float*)d_in[1];
    const float* Wk = (const float*)d_in[2];
    const float* Wv = (const float*)d_in[3];
    const float* Wo = (const float*)d_in[4];
    const float* rb = (const float*)d_in[5];
    float* out = (float*)d_out;

    // 1) relative-position bias table
    {
        int total = CH * BIAS_LEN;
        bias_table_kernel<<<(total + 255) / 256, 256>>>(rb);
    }
    // 2) fused QKV projections (grid.z selects W / destination)
    {
        dim3 grid(CD / GBN, (CB * CS) / GBM, 3);
        qkv_kernel<<<grid, 256>>>(X, Wq, Wk, Wv);
    }
    // 3) fused flash attention
    {
        cudaFuncSetAttribute(attn_kernel,
                             cudaFuncAttributeMaxDynamicSharedMemorySize,
                             (int)sizeof(AttnSmem));
        dim3 grid(CS / AQ, CH, CB);
        attn_kernel<<<grid, 256, sizeof(AttnSmem)>>>();
    }
    // 4) output projection -> d_out
    {
        dim3 grid(CD / GBN, (CB * CS) / GBM);
        out_proj_kernel<<<grid, 256>>>(Wo, out);
    }
}